// round 2
// baseline (speedup 1.0000x reference)
#include <cuda_runtime.h>

#define N_TOK 32768
#define DIM   256
#define NC    8192
#define BM    128
#define BN    128
#define BK    32
#define NSPLIT 4
#define CPC   (NC / NSPLIT)      // codes per CTA = 2048
#define NTILES (CPC / BN)        // 16

// ---- device scratch (static, allocation-free) ----
__device__ float g_zT[DIM * N_TOK];                    // [dim][token]  32 MB
__device__ float g_qc[NC * DIM];                       // [code][dim]    8 MB
__device__ float g_qcT[DIM * NC];                      // [dim][code]    8 MB
__device__ float g_cn[NC];                             // ||c||^2 (fp32)
__device__ float g_z2[N_TOK];                          // ||z||^2 (fp64-accurate, fp32-rounded)
__device__ unsigned long long g_part[N_TOK * NSPLIT];  // packed (dist,idx) partials
__device__ int g_idx[N_TOK];

// ---------------- kernel 0: transpose z -> zT ----------------
__global__ void k_transpose(const float* __restrict__ z) {
    __shared__ float t[32][33];
    int d0 = blockIdx.x * 32;
    int n0 = blockIdx.y * 32;
    int tx = threadIdx.x, ty = threadIdx.y;  // block (32,8)
#pragma unroll
    for (int j = 0; j < 32; j += 8)
        t[ty + j][tx] = z[(size_t)(n0 + ty + j) * DIM + d0 + tx];
    __syncthreads();
#pragma unroll
    for (int j = 0; j < 32; j += 8)
        g_zT[(size_t)(d0 + ty + j) * N_TOK + n0 + tx] = t[tx][ty + j];
}

// ---------------- kernel 0b: token norms ||z||^2 in fp64 ----------------
// One warp per token: 256 floats = 2 float4 per lane, fp64 accumulate + shfl reduce.
__global__ void k_z2(const float* __restrict__ z) {
    int warp = (blockIdx.x * blockDim.x + threadIdx.x) >> 5;
    int lane = threadIdx.x & 31;
    if (warp >= N_TOK) return;
    const float4* r = (const float4*)&z[(size_t)warp * DIM];
    double s = 0.0;
#pragma unroll
    for (int i = 0; i < 2; i++) {
        float4 v = r[lane + i * 32];
        s += (double)v.x * v.x + (double)v.y * v.y +
             (double)v.z * v.z + (double)v.w * v.w;
    }
#pragma unroll
    for (int o = 16; o > 0; o >>= 1) s += __shfl_down_sync(0xFFFFFFFFu, s, o);
    if (lane == 0) g_z2[warp] = (float)s;
}

// ---------------- kernel 1: qc = cb @ pw^T + pb  (also writes qcT) ----------------
__global__ __launch_bounds__(256) void k_proj(const float* __restrict__ cb,
                                              const float* __restrict__ pw,
                                              const float* __restrict__ pb) {
    __shared__ float As[16][65];  // [j][k_local]
    __shared__ float Bs[16][65];  // [j][d_local]
    int k0 = blockIdx.x * 64;
    int d0 = blockIdx.y * 64;
    int tid = threadIdx.x;
    int ty = tid >> 4, tx = tid & 15;
    float acc[4][4];
#pragma unroll
    for (int i = 0; i < 4; i++)
#pragma unroll
        for (int l = 0; l < 4; l++) acc[i][l] = 0.0f;

    for (int c = 0; c < DIM / 16; c++) {
        int kl = tid >> 2, j4 = tid & 3;
        float4 v = *(const float4*)&cb[(size_t)(k0 + kl) * DIM + c * 16 + j4 * 4];
        As[j4 * 4 + 0][kl] = v.x; As[j4 * 4 + 1][kl] = v.y;
        As[j4 * 4 + 2][kl] = v.z; As[j4 * 4 + 3][kl] = v.w;
        float4 w = *(const float4*)&pw[(size_t)(d0 + kl) * DIM + c * 16 + j4 * 4];
        Bs[j4 * 4 + 0][kl] = w.x; Bs[j4 * 4 + 1][kl] = w.y;
        Bs[j4 * 4 + 2][kl] = w.z; Bs[j4 * 4 + 3][kl] = w.w;
        __syncthreads();
#pragma unroll
        for (int j = 0; j < 16; j++) {
            float a[4], b[4];
#pragma unroll
            for (int i = 0; i < 4; i++) a[i] = As[j][ty * 4 + i];
#pragma unroll
            for (int i = 0; i < 4; i++) b[i] = Bs[j][tx * 4 + i];
#pragma unroll
            for (int i = 0; i < 4; i++)
#pragma unroll
                for (int l = 0; l < 4; l++) acc[i][l] += a[i] * b[l];
        }
        __syncthreads();
    }
#pragma unroll
    for (int i = 0; i < 4; i++) {
        int kg = k0 + ty * 4 + i;
#pragma unroll
        for (int l = 0; l < 4; l++) {
            int dg = d0 + tx * 4 + l;
            float v = acc[i][l] + pb[dg];
            g_qc[(size_t)kg * DIM + dg] = v;
            g_qcT[(size_t)dg * NC + kg] = v;
        }
    }
}

// ---------------- kernel 2: code norms ----------------
__global__ void k_cn() {
    int k = blockIdx.x * 256 + threadIdx.x;
    if (k >= NC) return;
    const float4* r = (const float4*)&g_qc[(size_t)k * DIM];
    float s = 0.0f;
#pragma unroll
    for (int i = 0; i < DIM / 4; i++) {
        float4 v = r[i];
        s += v.x * v.x + v.y * v.y + v.z * v.z + v.w * v.w;
    }
    g_cn[k] = s;
}

// ---------------- kernel 3: fused distance GEMM + argmin ----------------
// CTA: 128 tokens (z tile resident in smem) x 2048 codes (streamed).
// d = fl32( fl32(||z||^2 + ||c||^2) - 2 z.c )  -- replicates reference rounding,
// argmin with exact first-index tie-break via packed u64.
__global__ __launch_bounds__(256, 1) void k_dist() {
    extern __shared__ float sm[];
    float* As = sm;                 // [DIM][BM]       128 KB, resident
    float* Bs = sm + DIM * BM;      // [2][BK][BN]     32 KB, double-buffered

    int tid = threadIdx.x;
    int tileM = blockIdx.x >> 2;          // token tile 0..255
    int split = blockIdx.x & (NSPLIT - 1);
    int tok0 = tileM * BM;
    int code0 = split * CPC;

    // Load resident A tile: As[k][t] from zT (fully coalesced, conflict-free STS.128)
#pragma unroll
    for (int v = 0; v < 32; v++) {
        int u = tid + v * 256;            // 8192 float4s
        int k = u >> 5, f = u & 31;
        *(float4*)&As[k * BM + f * 4] =
            *(const float4*)&g_zT[(size_t)k * N_TOK + tok0 + f * 4];
    }

    int ty = tid >> 4, tx = tid & 15;
    int rA0 = ty * 4, rA1 = rA0 + 64;
    int cB0 = tx * 4, cB1 = cB0 + 64;

    // per-row token norms (constant across code tiles)
    float z2i[8];
#pragma unroll
    for (int i = 0; i < 8; i++) {
        int tr = (i < 4) ? (rA0 + i) : (rA1 + i - 4);
        z2i[i] = __ldg(&g_z2[tok0 + tr]);
    }

    unsigned long long best[8];
#pragma unroll
    for (int i = 0; i < 8; i++) best[i] = ~0ull;

    for (int nt = 0; nt < NTILES; nt++) {
        int cbase = code0 + nt * BN;
        float acc[8][8];
#pragma unroll
        for (int i = 0; i < 8; i++)
#pragma unroll
            for (int j = 0; j < 8; j++) acc[i][j] = 0.0f;

        float4 pre[4];
        // prologue: chunk 0
#pragma unroll
        for (int v = 0; v < 4; v++) {
            int u = tid + v * 256;
            int k = u >> 5, c = u & 31;
            pre[v] = *(const float4*)&g_qcT[(size_t)(0 * BK + k) * NC + cbase + c * 4];
        }
        __syncthreads();  // As ready (nt==0) / Bs free (nt>0)
#pragma unroll
        for (int v = 0; v < 4; v++) {
            int u = tid + v * 256;
            int k = u >> 5, c = u & 31;
            *(float4*)&Bs[k * BN + c * 4] = pre[v];
        }
        __syncthreads();

        for (int ck = 0; ck < DIM / BK; ck++) {
            if (ck + 1 < DIM / BK) {
#pragma unroll
                for (int v = 0; v < 4; v++) {
                    int u = tid + v * 256;
                    int k = u >> 5, c = u & 31;
                    pre[v] = *(const float4*)
                        &g_qcT[(size_t)((ck + 1) * BK + k) * NC + cbase + c * 4];
                }
            }
            const float* Bp = Bs + (ck & 1) * BK * BN;
            const float* Ap = As + ck * BK * BM;
#pragma unroll
            for (int k = 0; k < BK; k++) {
                float4 a0 = *(const float4*)&Ap[k * BM + rA0];
                float4 a1 = *(const float4*)&Ap[k * BM + rA1];
                float4 b0 = *(const float4*)&Bp[k * BN + cB0];
                float4 b1 = *(const float4*)&Bp[k * BN + cB1];
                float a[8] = {a0.x, a0.y, a0.z, a0.w, a1.x, a1.y, a1.z, a1.w};
                float b[8] = {b0.x, b0.y, b0.z, b0.w, b1.x, b1.y, b1.z, b1.w};
#pragma unroll
                for (int i = 0; i < 8; i++)
#pragma unroll
                    for (int j = 0; j < 8; j++) acc[i][j] += a[i] * b[j];
            }
            if (ck + 1 < DIM / BK) {
                float* Bn = Bs + ((ck + 1) & 1) * BK * BN;
#pragma unroll
                for (int v = 0; v < 4; v++) {
                    int u = tid + v * 256;
                    int k = u >> 5, c = u & 31;
                    *(float4*)&Bn[k * BN + c * 4] = pre[v];
                }
            }
            __syncthreads();
        }

        // epilogue: replicate reference rounding, packed argmin update
        float cnj[8];
#pragma unroll
        for (int j = 0; j < 8; j++) {
            int code = cbase + ((j < 4) ? cB0 + j : cB1 + j - 4);
            cnj[j] = __ldg(&g_cn[code]);
        }
#pragma unroll
        for (int i = 0; i < 8; i++) {
#pragma unroll
            for (int j = 0; j < 8; j++) {
                float t = __fadd_rn(z2i[i], cnj[j]);           // fl(z2 + c2)
                float d = __fadd_rn(t, -2.0f * acc[i][j]);     // fl(.. - 2 z.c)
                unsigned ub = __float_as_uint(d);
                ub = (ub & 0x80000000u) ? ~ub : (ub | 0x80000000u);  // order-preserving
                int code = cbase + ((j < 4) ? cB0 + j : cB1 + j - 4);
                unsigned long long p = ((unsigned long long)ub << 32) | (unsigned)code;
                best[i] = (p < best[i]) ? p : best[i];
            }
        }
    }

    // cross-thread reduction over the 16 column-threads sharing each token row
    __syncthreads();
    unsigned long long* red = (unsigned long long*)Bs;  // 128 x 16 u64 = 16 KB (fits in Bs)
#pragma unroll
    for (int i = 0; i < 8; i++) {
        int tr = (i < 4) ? (rA0 + i) : (rA1 + i - 4);
        red[tr * 16 + tx] = best[i];
    }
    __syncthreads();
    if (tid < BM) {
        unsigned long long m = red[tid * 16];
#pragma unroll
        for (int s = 1; s < 16; s++) {
            unsigned long long v = red[tid * 16 + s];
            m = (v < m) ? v : m;
        }
        g_part[(size_t)(tok0 + tid) * NSPLIT + split] = m;
    }
}

// ---------------- kernel 4: reduce splits -> indices ----------------
__global__ void k_argmin(float* __restrict__ idx_out, int do_write) {
    int n = blockIdx.x * 256 + threadIdx.x;
    if (n >= N_TOK) return;
    unsigned long long m = g_part[(size_t)n * NSPLIT];
#pragma unroll
    for (int s = 1; s < NSPLIT; s++) {
        unsigned long long v = g_part[(size_t)n * NSPLIT + s];
        m = (v < m) ? v : m;
    }
    int idx = (int)(unsigned)(m & 0xFFFFFFFFull);
    g_idx[n] = idx;
    if (do_write) idx_out[n] = (float)idx;
}

// ---------------- kernel 5: gather z_q ----------------
__global__ void k_gather(float4* __restrict__ out) {
    int g = blockIdx.x * 256 + threadIdx.x;  // over N_TOK * 64 float4s
    if (g >= N_TOK * (DIM / 4)) return;
    int tok = g >> 6, f = g & 63;
    out[g] = *(const float4*)&g_qc[(size_t)g_idx[tok] * DIM + f * 4];
}

// ---------------- launch ----------------
extern "C" void kernel_launch(void* const* d_in, const int* in_sizes, int n_in,
                              void* d_out, int out_size) {
    const float* z  = (const float*)d_in[0];
    const float* cb = (const float*)d_in[1];
    const float* pw = (const float*)d_in[2];
    const float* pb = (const float*)d_in[3];
    float* out = (float*)d_out;

    k_transpose<<<dim3(DIM / 32, N_TOK / 32), dim3(32, 8)>>>(z);
    k_z2<<<(N_TOK * 32) / 256, 256>>>(z);
    k_proj<<<dim3(NC / 64, DIM / 64), 256>>>(cb, pw, pb);
    k_cn<<<NC / 256, 256>>>();

    int smem = (DIM * BM + 2 * BK * BN) * (int)sizeof(float);  // 160 KB
    cudaFuncSetAttribute(k_dist, cudaFuncAttributeMaxDynamicSharedMemorySize, smem);
    k_dist<<<(N_TOK / BM) * NSPLIT, 256, smem>>>();

    int do_write = (out_size >= N_TOK * DIM + N_TOK);
    k_argmin<<<N_TOK / 256, 256>>>(out + (size_t)N_TOK * DIM, do_write);
    k_gather<<<(N_TOK * (DIM / 4) + 255) / 256, 256>>>((float4*)out);
}

// round 5
// speedup vs baseline: 1.0923x; 1.0923x over previous
#include <cuda_runtime.h>

#define N_TOK 32768
#define DIM   256
#define NC    8192
#define BM    128
#define BN    128
#define BK    32
#define NSPLIT 4
#define CPC   (NC / NSPLIT)      // codes per CTA = 2048
#define NTILES (CPC / BN)        // 16

#if defined(__CUDA_ARCH__) && (__CUDA_ARCH__ >= 1000)
#define HAS_F32X2 1
#else
#define HAS_F32X2 0
#endif

// packed fp32x2 helpers (Blackwell FFMA2 path — ptxas never auto-fuses this).
// Fallback keeps bit-identical semantics (two independent IEEE fp32 FMAs).
struct f2 { float lo, hi; };

__device__ __forceinline__ unsigned long long pack2(float x, float y) {
#if HAS_F32X2
    unsigned long long d;
    asm("mov.b64 %0, {%1, %2};" : "=l"(d) : "f"(x), "f"(y));
    return d;
#else
    union { unsigned long long u; f2 f; } c; c.f.lo = x; c.f.hi = y; return c.u;
#endif
}
__device__ __forceinline__ void fma2(unsigned long long& acc,
                                     unsigned long long a, unsigned long long b) {
#if HAS_F32X2
    asm("fma.rn.f32x2 %0, %1, %2, %0;" : "+l"(acc) : "l"(a), "l"(b));
#else
    union { unsigned long long u; f2 f; } ca, cb, cc;
    ca.u = a; cb.u = b; cc.u = acc;
    cc.f.lo = __fmaf_rn(ca.f.lo, cb.f.lo, cc.f.lo);
    cc.f.hi = __fmaf_rn(ca.f.hi, cb.f.hi, cc.f.hi);
    acc = cc.u;
#endif
}
__device__ __forceinline__ void unpack2(float& x, float& y, unsigned long long d) {
#if HAS_F32X2
    asm("mov.b64 {%0, %1}, %2;" : "=f"(x), "=f"(y) : "l"(d));
#else
    union { unsigned long long u; f2 f; } c; c.u = d; x = c.f.lo; y = c.f.hi;
#endif
}

// ---- device scratch (static, allocation-free) ----
__device__ float g_zT[DIM * N_TOK];                    // [dim][token]  32 MB
__device__ float g_qc[NC * DIM];                       // [code][dim]    8 MB
__device__ float g_qcT[DIM * NC];                      // [dim][code]    8 MB
__device__ float g_cn[NC];                             // ||c||^2 (fp32)
__device__ float g_z2[N_TOK];                          // ||z||^2 (fp64-accurate, fp32-rounded)
__device__ unsigned long long g_part[N_TOK * NSPLIT];  // packed (dist,idx) partials
__device__ int g_idx[N_TOK];

// ---------------- kernel 0: transpose z -> zT ----------------
__global__ void k_transpose(const float* __restrict__ z) {
    __shared__ float t[32][33];
    int d0 = blockIdx.x * 32;
    int n0 = blockIdx.y * 32;
    int tx = threadIdx.x, ty = threadIdx.y;  // block (32,8)
#pragma unroll
    for (int j = 0; j < 32; j += 8)
        t[ty + j][tx] = z[(size_t)(n0 + ty + j) * DIM + d0 + tx];
    __syncthreads();
#pragma unroll
    for (int j = 0; j < 32; j += 8)
        g_zT[(size_t)(d0 + ty + j) * N_TOK + n0 + tx] = t[tx][ty + j];
}

// ---------------- kernel 0b: token norms ||z||^2 in fp64 ----------------
__global__ void k_z2(const float* __restrict__ z) {
    int warp = (blockIdx.x * blockDim.x + threadIdx.x) >> 5;
    int lane = threadIdx.x & 31;
    if (warp >= N_TOK) return;
    const float4* r = (const float4*)&z[(size_t)warp * DIM];
    double s = 0.0;
#pragma unroll
    for (int i = 0; i < 2; i++) {
        float4 v = r[lane + i * 32];
        s += (double)v.x * v.x + (double)v.y * v.y +
             (double)v.z * v.z + (double)v.w * v.w;
    }
#pragma unroll
    for (int o = 16; o > 0; o >>= 1) s += __shfl_down_sync(0xFFFFFFFFu, s, o);
    if (lane == 0) g_z2[warp] = (float)s;
}

// ---------------- kernel 1: qc = cb @ pw^T + pb  (also writes qcT) ----------------
__global__ __launch_bounds__(256) void k_proj(const float* __restrict__ cb,
                                              const float* __restrict__ pw,
                                              const float* __restrict__ pb) {
    __shared__ float As[16][65];  // [j][k_local]
    __shared__ float Bs[16][65];  // [j][d_local]
    int k0 = blockIdx.x * 64;
    int d0 = blockIdx.y * 64;
    int tid = threadIdx.x;
    int ty = tid >> 4, tx = tid & 15;
    float acc[4][4];
#pragma unroll
    for (int i = 0; i < 4; i++)
#pragma unroll
        for (int l = 0; l < 4; l++) acc[i][l] = 0.0f;

    for (int c = 0; c < DIM / 16; c++) {
        int kl = tid >> 2, j4 = tid & 3;
        float4 v = *(const float4*)&cb[(size_t)(k0 + kl) * DIM + c * 16 + j4 * 4];
        As[j4 * 4 + 0][kl] = v.x; As[j4 * 4 + 1][kl] = v.y;
        As[j4 * 4 + 2][kl] = v.z; As[j4 * 4 + 3][kl] = v.w;
        float4 w = *(const float4*)&pw[(size_t)(d0 + kl) * DIM + c * 16 + j4 * 4];
        Bs[j4 * 4 + 0][kl] = w.x; Bs[j4 * 4 + 1][kl] = w.y;
        Bs[j4 * 4 + 2][kl] = w.z; Bs[j4 * 4 + 3][kl] = w.w;
        __syncthreads();
#pragma unroll
        for (int j = 0; j < 16; j++) {
            float a[4], b[4];
#pragma unroll
            for (int i = 0; i < 4; i++) a[i] = As[j][ty * 4 + i];
#pragma unroll
            for (int i = 0; i < 4; i++) b[i] = Bs[j][tx * 4 + i];
#pragma unroll
            for (int i = 0; i < 4; i++)
#pragma unroll
                for (int l = 0; l < 4; l++) acc[i][l] += a[i] * b[l];
        }
        __syncthreads();
    }
#pragma unroll
    for (int i = 0; i < 4; i++) {
        int kg = k0 + ty * 4 + i;
#pragma unroll
        for (int l = 0; l < 4; l++) {
            int dg = d0 + tx * 4 + l;
            float v = acc[i][l] + pb[dg];
            g_qc[(size_t)kg * DIM + dg] = v;
            g_qcT[(size_t)dg * NC + kg] = v;
        }
    }
}

// ---------------- kernel 2: code norms ----------------
__global__ void k_cn() {
    int k = blockIdx.x * 256 + threadIdx.x;
    if (k >= NC) return;
    const float4* r = (const float4*)&g_qc[(size_t)k * DIM];
    float s = 0.0f;
#pragma unroll
    for (int i = 0; i < DIM / 4; i++) {
        float4 v = r[i];
        s += v.x * v.x + v.y * v.y + v.z * v.z + v.w * v.w;
    }
    g_cn[k] = s;
}

// ---------------- kernel 3: fused distance GEMM + argmin (packed f32x2) ----------------
// CTA: 128 tokens (z tile resident in smem) x 2048 codes (streamed).
// d = fl32( fl32(||z||^2 + ||c||^2) - 2 z.c )  -- replicates reference rounding.
// Inner product via fma.rn.f32x2 (FFMA2): bit-identical to scalar FFMA, 2x rate.
__global__ __launch_bounds__(256, 1) void k_dist() {
    extern __shared__ float sm[];
    float* As = sm;                 // [DIM][BM]       128 KB, resident
    float* Bs = sm + DIM * BM;      // [2][BK][BN]     32 KB, double-buffered

    int tid = threadIdx.x;
    int tileM = blockIdx.x >> 2;          // token tile 0..255
    int split = blockIdx.x & (NSPLIT - 1);
    int tok0 = tileM * BM;
    int code0 = split * CPC;

    // Load resident A tile: As[k][t] from zT (fully coalesced, conflict-free)
#pragma unroll
    for (int v = 0; v < 32; v++) {
        int u = tid + v * 256;            // 8192 float4s
        int k = u >> 5, f = u & 31;
        *(float4*)&As[k * BM + f * 4] =
            *(const float4*)&g_zT[(size_t)k * N_TOK + tok0 + f * 4];
    }

    int ty = tid >> 4, tx = tid & 15;
    int rA0 = ty * 4, rA1 = rA0 + 64;
    int cB0 = tx * 4, cB1 = cB0 + 64;

    // per-row token norms (constant across code tiles)
    float z2i[8];
#pragma unroll
    for (int i = 0; i < 8; i++) {
        int tr = (i < 4) ? (rA0 + i) : (rA1 + i - 4);
        z2i[i] = __ldg(&g_z2[tok0 + tr]);
    }

    unsigned long long best[8];
#pragma unroll
    for (int i = 0; i < 8; i++) best[i] = ~0ull;

    for (int nt = 0; nt < NTILES; nt++) {
        int cbase = code0 + nt * BN;
        unsigned long long acc2[8][4];    // [row][code-pair], packed f32x2
#pragma unroll
        for (int i = 0; i < 8; i++)
#pragma unroll
            for (int jp = 0; jp < 4; jp++) acc2[i][jp] = 0ull;

        float4 pre[4];
        // prologue: chunk 0
#pragma unroll
        for (int v = 0; v < 4; v++) {
            int u = tid + v * 256;
            int k = u >> 5, c = u & 31;
            pre[v] = *(const float4*)&g_qcT[(size_t)(0 * BK + k) * NC + cbase + c * 4];
        }
        __syncthreads();  // As ready (nt==0) / Bs free (nt>0)
#pragma unroll
        for (int v = 0; v < 4; v++) {
            int u = tid + v * 256;
            int k = u >> 5, c = u & 31;
            *(float4*)&Bs[k * BN + c * 4] = pre[v];
        }
        __syncthreads();

        for (int ck = 0; ck < DIM / BK; ck++) {
            if (ck + 1 < DIM / BK) {
#pragma unroll
                for (int v = 0; v < 4; v++) {
                    int u = tid + v * 256;
                    int k = u >> 5, c = u & 31;
                    pre[v] = *(const float4*)
                        &g_qcT[(size_t)((ck + 1) * BK + k) * NC + cbase + c * 4];
                }
            }
            const float* Bp = Bs + (ck & 1) * BK * BN;
            const float* Ap = As + ck * BK * BM;
#pragma unroll
            for (int k = 0; k < BK; k++) {
                float4 a0 = *(const float4*)&Ap[k * BM + rA0];
                float4 a1 = *(const float4*)&Ap[k * BM + rA1];
                float4 b0 = *(const float4*)&Bp[k * BN + cB0];
                float4 b1 = *(const float4*)&Bp[k * BN + cB1];
                unsigned long long ap[8], bp[4];
                ap[0] = pack2(a0.x, a0.x); ap[1] = pack2(a0.y, a0.y);
                ap[2] = pack2(a0.z, a0.z); ap[3] = pack2(a0.w, a0.w);
                ap[4] = pack2(a1.x, a1.x); ap[5] = pack2(a1.y, a1.y);
                ap[6] = pack2(a1.z, a1.z); ap[7] = pack2(a1.w, a1.w);
                bp[0] = pack2(b0.x, b0.y); bp[1] = pack2(b0.z, b0.w);
                bp[2] = pack2(b1.x, b1.y); bp[3] = pack2(b1.z, b1.w);
#pragma unroll
                for (int i = 0; i < 8; i++) {
                    fma2(acc2[i][0], ap[i], bp[0]);
                    fma2(acc2[i][1], ap[i], bp[1]);
                    fma2(acc2[i][2], ap[i], bp[2]);
                    fma2(acc2[i][3], ap[i], bp[3]);
                }
            }
            if (ck + 1 < DIM / BK) {
                float* Bn = Bs + ((ck + 1) & 1) * BK * BN;
#pragma unroll
                for (int v = 0; v < 4; v++) {
                    int u = tid + v * 256;
                    int k = u >> 5, c = u & 31;
                    *(float4*)&Bn[k * BN + c * 4] = pre[v];
                }
            }
            __syncthreads();
        }

        // epilogue: replicate reference rounding, packed argmin update
        float cnj[8];
#pragma unroll
        for (int j = 0; j < 8; j++) {
            int code = cbase + ((j < 4) ? cB0 + j : cB1 + j - 4);
            cnj[j] = __ldg(&g_cn[code]);
        }
#pragma unroll
        for (int i = 0; i < 8; i++) {
#pragma unroll
            for (int jp = 0; jp < 4; jp++) {
                float dlo, dhi;
                unpack2(dlo, dhi, acc2[i][jp]);
#pragma unroll
                for (int h = 0; h < 2; h++) {
                    int j = jp * 2 + h;
                    float dot = h ? dhi : dlo;
                    float t = __fadd_rn(z2i[i], cnj[j]);        // fl(z2 + c2)
                    float d = __fadd_rn(t, -2.0f * dot);        // fl(.. - 2 z.c)
                    unsigned ub = __float_as_uint(d);
                    ub = (ub & 0x80000000u) ? ~ub : (ub | 0x80000000u);
                    int code = cbase + ((j < 4) ? cB0 + j : cB1 + j - 4);
                    unsigned long long p =
                        ((unsigned long long)ub << 32) | (unsigned)code;
                    best[i] = (p < best[i]) ? p : best[i];
                }
            }
        }
    }

    // cross-thread reduction over the 16 column-threads sharing each token row
    __syncthreads();
    unsigned long long* red = (unsigned long long*)Bs;  // 128 x 16 u64 = 16 KB
#pragma unroll
    for (int i = 0; i < 8; i++) {
        int tr = (i < 4) ? (rA0 + i) : (rA1 + i - 4);
        red[tr * 16 + tx] = best[i];
    }
    __syncthreads();
    if (tid < BM) {
        unsigned long long m = red[tid * 16];
#pragma unroll
        for (int s = 1; s < 16; s++) {
            unsigned long long v = red[tid * 16 + s];
            m = (v < m) ? v : m;
        }
        g_part[(size_t)(tok0 + tid) * NSPLIT + split] = m;
    }
}

// ---------------- kernel 4: reduce splits -> indices ----------------
__global__ void k_argmin(float* __restrict__ idx_out, int do_write) {
    int n = blockIdx.x * 256 + threadIdx.x;
    if (n >= N_TOK) return;
    unsigned long long m = g_part[(size_t)n * NSPLIT];
#pragma unroll
    for (int s = 1; s < NSPLIT; s++) {
        unsigned long long v = g_part[(size_t)n * NSPLIT + s];
        m = (v < m) ? v : m;
    }
    int idx = (int)(unsigned)(m & 0xFFFFFFFFull);
    g_idx[n] = idx;
    if (do_write) idx_out[n] = (float)idx;
}

// ---------------- kernel 5: gather z_q ----------------
__global__ void k_gather(float4* __restrict__ out) {
    int g = blockIdx.x * 256 + threadIdx.x;  // over N_TOK * 64 float4s
    if (g >= N_TOK * (DIM / 4)) return;
    int tok = g >> 6, f = g & 63;
    out[g] = *(const float4*)&g_qc[(size_t)g_idx[tok] * DIM + f * 4];
}

// ---------------- launch ----------------
extern "C" void kernel_launch(void* const* d_in, const int* in_sizes, int n_in,
                              void* d_out, int out_size) {
    const float* z  = (const float*)d_in[0];
    const float* cb = (const float*)d_in[1];
    const float* pw = (const float*)d_in[2];
    const float* pb = (const float*)d_in[3];
    float* out = (float*)d_out;

    k_transpose<<<dim3(DIM / 32, N_TOK / 32), dim3(32, 8)>>>(z);
    k_z2<<<(N_TOK * 32) / 256, 256>>>(z);
    k_proj<<<dim3(NC / 64, DIM / 64), 256>>>(cb, pw, pb);
    k_cn<<<NC / 256, 256>>>();

    int smem = (DIM * BM + 2 * BK * BN) * (int)sizeof(float);  // 160 KB
    cudaFuncSetAttribute(k_dist, cudaFuncAttributeMaxDynamicSharedMemorySize, smem);
    k_dist<<<(N_TOK / BM) * NSPLIT, 256, smem>>>();

    int do_write = (out_size >= N_TOK * DIM + N_TOK);
    k_argmin<<<N_TOK / 256, 256>>>(out + (size_t)N_TOK * DIM, do_write);
    k_gather<<<(N_TOK * (DIM / 4) + 255) / 256, 256>>>((float4*)out);
}